// round 1
// baseline (speedup 1.0000x reference)
#include <cuda_runtime.h>
#include <cuda_bf16.h>
#include <math.h>

// ----------------------------------------------------------------------------
// GraphSAGE (3 layers) + up-proj + tri-pooling + MLP head.
// N=100000 nodes, E=1600000 edges, G=256 graphs, H=32, UP=128, out 51.
// All scratch in __device__ globals (no allocation).
// ----------------------------------------------------------------------------

#define MAXN 100000
#define MAXE 1600000
#define MAXG 256

__device__ int   g_src[MAXE];
__device__ int   g_dst[MAXE];
__device__ float g_deg[MAXN];
__device__ float g_agg1[MAXN];
__device__ float g_h1[MAXN * 32];
__device__ float g_agg[MAXN * 32];
__device__ float g_h2[MAXN * 32];
__device__ float g_h4[(size_t)MAXN * 128];
__device__ int   g_start[MAXG + 1];
__device__ float g_z[MAXG * 384];
__device__ int   g_flags[2];   // [0]=edge_index is int64, [1]=batch is int64

__device__ __forceinline__ float lrelu(float v) { return v > 0.f ? v : 0.01f * v; }

// ---------------------------------------------------------------------------
// Dtype sniffing: int64 little-endian nonneg small values => odd 32-bit words 0.
// edges: check words [1,3,...,63]. batch: check odd words in [base, base+64)
// (base even, near the end where sorted batch values are ~255, nonzero if i32).
// ---------------------------------------------------------------------------
__global__ void k_detect(const unsigned int* __restrict__ ew,
                         const unsigned int* __restrict__ bw, int bbase) {
    if (threadIdx.x == 0) {
        int e64 = 1;
        for (int i = 1; i < 64; i += 2) if (ew[i] != 0u) { e64 = 0; break; }
        int b64 = 1;
        for (int i = 1; i < 64; i += 2) if (bw[bbase + i] != 0u) { b64 = 0; break; }
        g_flags[0] = e64;
        g_flags[1] = b64;
    }
}

__global__ void k_convert(const void* __restrict__ eidx, int E) {
    int i = blockIdx.x * blockDim.x + threadIdx.x;
    if (i >= E) return;
    if (g_flags[0]) {
        const long long* p = (const long long*)eidx;
        g_src[i] = (int)p[i];
        g_dst[i] = (int)p[(size_t)E + i];
    } else {
        const int* p = (const int*)eidx;
        g_src[i] = p[i];
        g_dst[i] = p[E + i];
    }
}

// ---------------------------------------------------------------------------
// Zeroing
// ---------------------------------------------------------------------------
__global__ void k_zero_all(int N) {
    int i = blockIdx.x * blockDim.x + threadIdx.x;
    if (i < N) { g_deg[i] = 0.f; g_agg1[i] = 0.f; }
    int total = N * 32;
    for (int j = i; j < total; j += gridDim.x * blockDim.x) g_agg[j] = 0.f;
}

__global__ void k_zero_agg(int N) {
    int i = blockIdx.x * blockDim.x + threadIdx.x;
    int total = N * 32;
    for (int j = i; j < total; j += gridDim.x * blockDim.x) g_agg[j] = 0.f;
}

// ---------------------------------------------------------------------------
// Layer 1 edge pass: scalar feature scatter-sum + in-degree count.
// ---------------------------------------------------------------------------
__global__ void k_edge1(const float* __restrict__ x, int E) {
    int i = blockIdx.x * blockDim.x + threadIdx.x;
    if (i >= E) return;
    int s = g_src[i], d = g_dst[i];
    atomicAdd(&g_agg1[d], __ldg(&x[s]));
    atomicAdd(&g_deg[d], 1.0f);
}

// h1[i][c] = lrelu(agg1[i]*W1l[c] + b1[c] + x[i]*W1r[c]);  8 threads/node (float4)
__global__ void k_h1(const float* __restrict__ x, const float* __restrict__ W1l,
                     const float* __restrict__ b1, const float* __restrict__ W1r,
                     int N) {
    int t = blockIdx.x * blockDim.x + threadIdx.x;
    if (t >= N * 8) return;
    int node = t >> 3, c = (t & 7) * 4;
    float a  = g_agg1[node];
    float xv = __ldg(&x[node]);
    float4 wl = *(const float4*)(W1l + c);
    float4 wr = *(const float4*)(W1r + c);
    float4 bb = *(const float4*)(b1 + c);
    float4 o;
    o.x = lrelu(a * wl.x + xv * wr.x + bb.x);
    o.y = lrelu(a * wl.y + xv * wr.y + bb.y);
    o.z = lrelu(a * wl.z + xv * wr.z + bb.z);
    o.w = lrelu(a * wl.w + xv * wr.w + bb.w);
    *(float4*)(g_h1 + node * 32 + c) = o;
}

// ---------------------------------------------------------------------------
// 32-channel edge scatter: 8 threads per edge, one float4 gather + vector RED.
// which==0 : read g_h1, which==1 : read g_h2. Accumulates into g_agg.
// ---------------------------------------------------------------------------
__global__ void k_scatter(int which, int E) {
    int t = blockIdx.x * blockDim.x + threadIdx.x;
    if (t >= E * 8) return;
    int e = t >> 3, c = t & 7;
    int s = g_src[e], d = g_dst[e];
    const float* h = which ? g_h2 : g_h1;
    float4 v = *(const float4*)(h + s * 32 + c * 4);
    float* addr = g_agg + d * 32 + c * 4;
    asm volatile("red.global.add.v4.f32 [%0], {%1,%2,%3,%4};"
                 :: "l"(addr), "f"(v.x), "f"(v.y), "f"(v.z), "f"(v.w)
                 : "memory");
}

// ---------------------------------------------------------------------------
// Layer-2 node transform: h2 = lrelu(agg@W2l + b2 + h1@W2r). Warp per node.
// ---------------------------------------------------------------------------
__global__ void k_sage2(const float* __restrict__ Wl, const float* __restrict__ b,
                        const float* __restrict__ Wr, int N) {
    __shared__ float sWl[1024], sWr[1024], sb[32];
    for (int i = threadIdx.x; i < 1024; i += blockDim.x) { sWl[i] = Wl[i]; sWr[i] = Wr[i]; }
    if (threadIdx.x < 32) sb[threadIdx.x] = b[threadIdx.x];
    __syncthreads();
    int lane = threadIdx.x & 31;
    int warp = (blockIdx.x * blockDim.x + threadIdx.x) >> 5;
    int nw = (gridDim.x * blockDim.x) >> 5;
    for (int node = warp; node < N; node += nw) {
        float a  = g_agg[node * 32 + lane];
        float hv = g_h1[node * 32 + lane];
        float acc = sb[lane];
        #pragma unroll
        for (int k = 0; k < 32; k++) {
            acc += __shfl_sync(0xffffffffu, a, k)  * sWl[k * 32 + lane]
                 + __shfl_sync(0xffffffffu, hv, k) * sWr[k * 32 + lane];
        }
        g_h2[node * 32 + lane] = lrelu(acc);
    }
}

// ---------------------------------------------------------------------------
// Layer-3 node transform (mean aggr) fused with up-projection 32->128.
// h3 = lrelu((agg/deg)@W3l + b3 + h2@W3r);  h4 = lrelu(h3@Wu + bu)  [N,128]
// ---------------------------------------------------------------------------
__global__ void k_sage3up(const float* __restrict__ W3l, const float* __restrict__ b3,
                          const float* __restrict__ W3r, const float* __restrict__ Wu,
                          const float* __restrict__ bu, int N) {
    __shared__ float sWl[1024], sWr[1024], sWu[4096], sb[32], sbu[128];
    for (int i = threadIdx.x; i < 1024; i += blockDim.x) { sWl[i] = W3l[i]; sWr[i] = W3r[i]; }
    for (int i = threadIdx.x; i < 4096; i += blockDim.x) sWu[i] = Wu[i];
    if (threadIdx.x < 32)  sb[threadIdx.x]  = b3[threadIdx.x];
    if (threadIdx.x < 128) sbu[threadIdx.x] = bu[threadIdx.x];
    __syncthreads();
    int lane = threadIdx.x & 31;
    int warp = (blockIdx.x * blockDim.x + threadIdx.x) >> 5;
    int nw = (gridDim.x * blockDim.x) >> 5;
    for (int node = warp; node < N; node += nw) {
        float inv = 1.0f / fmaxf(g_deg[node], 1.0f);
        float a  = g_agg[node * 32 + lane] * inv;
        float hv = g_h2[node * 32 + lane];
        float acc = sb[lane];
        #pragma unroll
        for (int k = 0; k < 32; k++) {
            acc += __shfl_sync(0xffffffffu, a, k)  * sWl[k * 32 + lane]
                 + __shfl_sync(0xffffffffu, hv, k) * sWr[k * 32 + lane];
        }
        float h3 = lrelu(acc);
        float4 o = *(const float4*)(sbu + lane * 4);
        #pragma unroll
        for (int k = 0; k < 32; k++) {
            float hk = __shfl_sync(0xffffffffu, h3, k);
            float4 w = *(const float4*)(sWu + k * 128 + lane * 4);
            o.x += hk * w.x; o.y += hk * w.y; o.z += hk * w.z; o.w += hk * w.w;
        }
        o.x = lrelu(o.x); o.y = lrelu(o.y); o.z = lrelu(o.z); o.w = lrelu(o.w);
        *(float4*)(g_h4 + (size_t)node * 128 + lane * 4) = o;
    }
}

// ---------------------------------------------------------------------------
// Per-graph start offsets from the sorted batch array.
// ---------------------------------------------------------------------------
__global__ void k_starts(const void* __restrict__ batch, int N, int G) {
    int i = blockIdx.x * blockDim.x + threadIdx.x;
    if (i >= N) return;
    long long bi, bp;
    if (g_flags[1]) {
        const long long* p = (const long long*)batch;
        bi = p[i]; bp = (i == 0) ? -1LL : p[i - 1];
    } else {
        const int* p = (const int*)batch;
        bi = p[i]; bp = (i == 0) ? -1LL : p[i - 1];
    }
    if (bi != bp) for (long long g = bp + 1; g <= bi; g++) g_start[g] = i;
    if (i == N - 1) for (long long g = bi + 1; g <= G; g++) g_start[g] = N;
}

// ---------------------------------------------------------------------------
// Pooling: block per graph, 128 threads (one per channel), contiguous slab.
// z[g] = [mean(128) | max(128) | sum(128)]
// ---------------------------------------------------------------------------
__global__ void k_pool(int G) {
    int g = blockIdx.x;
    int c = threadIdx.x;
    int s = g_start[g], e = g_start[g + 1];
    float sum = 0.f, mx = -INFINITY;
    for (int i = s; i < e; i++) {
        float v = g_h4[(size_t)i * 128 + c];
        sum += v;
        mx = fmaxf(mx, v);
    }
    float cnt = (float)(e - s);
    g_z[g * 384 + c]       = sum / fmaxf(cnt, 1.0f);
    g_z[g * 384 + 128 + c] = mx;
    g_z[g * 384 + 256 + c] = sum;
}

// ---------------------------------------------------------------------------
// Head MLP: block per graph. z[384] -> lrelu(@Wf1+bf1)[128] -> @Wf2+bf2 [51]
// ---------------------------------------------------------------------------
__global__ void k_head(const float* __restrict__ Wf1, const float* __restrict__ bf1,
                       const float* __restrict__ Wf2, const float* __restrict__ bf2,
                       float* __restrict__ out, int G) {
    __shared__ float sz[384], sz2[128];
    int g = blockIdx.x;
    for (int i = threadIdx.x; i < 384; i += blockDim.x) sz[i] = g_z[g * 384 + i];
    __syncthreads();
    int c = threadIdx.x;
    float acc = bf1[c];
    #pragma unroll 4
    for (int k = 0; k < 384; k++) acc += sz[k] * Wf1[k * 128 + c];
    sz2[c] = lrelu(acc);
    __syncthreads();
    if (c < 51) {
        float o = bf2[c];
        #pragma unroll 4
        for (int k = 0; k < 128; k++) o += sz2[k] * Wf2[k * 51 + c];
        out[g * 51 + c] = o;
    }
}

// ---------------------------------------------------------------------------
extern "C" void kernel_launch(void* const* d_in, const int* in_sizes, int n_in,
                              void* d_out, int out_size) {
    const float* x    = (const float*)d_in[0];
    const void*  eidx = d_in[1];
    const void*  batch= d_in[2];
    const float* W1l  = (const float*)d_in[3];
    const float* b1   = (const float*)d_in[4];
    const float* W1r  = (const float*)d_in[5];
    const float* W2l  = (const float*)d_in[6];
    const float* b2   = (const float*)d_in[7];
    const float* W2r  = (const float*)d_in[8];
    const float* W3l  = (const float*)d_in[9];
    const float* b3   = (const float*)d_in[10];
    const float* W3r  = (const float*)d_in[11];
    const float* Wu   = (const float*)d_in[12];
    const float* bu   = (const float*)d_in[13];
    const float* Wf1  = (const float*)d_in[14];
    const float* bf1  = (const float*)d_in[15];
    const float* Wf2  = (const float*)d_in[16];
    const float* bf2  = (const float*)d_in[17];
    float* out = (float*)d_out;

    int N = in_sizes[0];
    int E = in_sizes[1] / 2;
    int G = out_size / 51;

    int bbase = (N - 64) & ~1;  // even base near the end of batch[]

    k_detect<<<1, 32>>>((const unsigned int*)eidx, (const unsigned int*)batch, bbase);
    k_convert<<<(E + 255) / 256, 256>>>(eidx, E);
    k_zero_all<<<(N * 32 + 255) / 256, 256>>>(N);
    k_edge1<<<(E + 255) / 256, 256>>>(x, E);
    k_h1<<<(N * 8 + 255) / 256, 256>>>(x, W1l, b1, W1r, N);
    k_scatter<<<(E * 8 + 255) / 256, 256>>>(0, E);
    k_sage2<<<1184, 256>>>(W2l, b2, W2r, N);
    k_zero_agg<<<(N * 32 + 255) / 256, 256>>>(N);
    k_scatter<<<(E * 8 + 255) / 256, 256>>>(1, E);
    k_sage3up<<<1184, 256>>>(W3l, b3, W3r, Wu, bu, N);
    k_starts<<<(N + 255) / 256, 256>>>(batch, N, G);
    k_pool<<<G, 128>>>(G);
    k_head<<<G, 128>>>(Wf1, bf1, Wf2, bf2, out, G);
}

// round 4
// speedup vs baseline: 1.0207x; 1.0207x over previous
#include <cuda_runtime.h>
#include <cuda_bf16.h>
#include <math.h>

// ----------------------------------------------------------------------------
// GraphSAGE (3 layers) + up-proj + tri-pooling + MLP head. CSR-gather version:
// no float atomics anywhere. N=100000, E=1600000, G=256, H=32, UP=128, out 51.
// ----------------------------------------------------------------------------

#define MAXN 100000
#define MAXE 1600000
#define MAXG 256
#define SCAN_BS 1024
#define MAX_SCAN_BLOCKS 128

__device__ int   g_src[MAXE];
__device__ int   g_dst[MAXE];
__device__ int   g_csr[MAXE];          // src ids grouped by dst
__device__ int   g_cnt[MAXN];          // in-degree histogram
__device__ int   g_rowptr[MAXN + 1];
__device__ int   g_cursor[MAXN];
__device__ int   g_bsum[MAX_SCAN_BLOCKS];
__device__ int   g_boff[MAX_SCAN_BLOCKS];
__device__ float g_h1[MAXN * 32];
__device__ float g_h2[MAXN * 32];
__device__ float g_h4[(size_t)MAXN * 128];
__device__ int   g_start[MAXG + 1];
__device__ float g_part[MAXG * 4 * 256];   // per (graph, quarter): [sum(128) | max(128)]
__device__ int   g_flags[2];   // [0]=edge_index is int64, [1]=batch is int64

__device__ __forceinline__ float lrelu(float v) { return v > 0.f ? v : 0.01f * v; }

// ---------------------------------------------------------------------------
// Dtype sniffing (int64 little-endian small nonneg => odd 32-bit words are 0)
// ---------------------------------------------------------------------------
__global__ void k_detect(const unsigned int* __restrict__ ew,
                         const unsigned int* __restrict__ bw, int bbase) {
    if (threadIdx.x == 0) {
        int e64 = 1;
        for (int i = 1; i < 64; i += 2) if (ew[i] != 0u) { e64 = 0; break; }
        int b64 = 1;
        for (int i = 1; i < 64; i += 2) if (bw[bbase + i] != 0u) { b64 = 0; break; }
        g_flags[0] = e64;
        g_flags[1] = b64;
    }
}

__global__ void k_zero_cnt(int N) {
    int i = blockIdx.x * blockDim.x + threadIdx.x;
    if (i < N) g_cnt[i] = 0;
}

// Convert edge index to int32 + build in-degree histogram (int atomics).
__global__ void k_convert_hist(const void* __restrict__ eidx, int E) {
    int i = blockIdx.x * blockDim.x + threadIdx.x;
    if (i >= E) return;
    int s, d;
    if (g_flags[0]) {
        const long long* p = (const long long*)eidx;
        s = (int)p[i];
        d = (int)p[(size_t)E + i];
    } else {
        const int* p = (const int*)eidx;
        s = p[i];
        d = p[E + i];
    }
    g_src[i] = s;
    g_dst[i] = d;
    atomicAdd(&g_cnt[d], 1);
}

// ---------------------------------------------------------------------------
// Exclusive scan of g_cnt into g_rowptr (3 kernels).
// ---------------------------------------------------------------------------
__global__ void k_scanA(int N) {
    __shared__ int sd[SCAN_BS];
    int b = blockIdx.x, t = threadIdx.x;
    int i = b * SCAN_BS + t;
    int v = (i < N) ? g_cnt[i] : 0;
    sd[t] = v;
    __syncthreads();
    for (int off = 1; off < SCAN_BS; off <<= 1) {
        int u = (t >= off) ? sd[t - off] : 0;
        __syncthreads();
        sd[t] += u;
        __syncthreads();
    }
    if (i < N) g_rowptr[i] = sd[t] - v;  // exclusive within block
    if (t == SCAN_BS - 1) g_bsum[b] = sd[t];
}

__global__ void k_scanB(int nblocks) {
    if (threadIdx.x == 0) {
        int run = 0;
        for (int b = 0; b < nblocks; b++) { g_boff[b] = run; run += g_bsum[b]; }
    }
}

__global__ void k_scanC(int N, int E) {
    int i = blockIdx.x * blockDim.x + threadIdx.x;
    if (i < N) {
        int r = g_rowptr[i] + g_boff[i / SCAN_BS];
        g_rowptr[i] = r;
        g_cursor[i] = r;
    }
    if (i == 0) g_rowptr[N] = E;
}

// Fill CSR: pos = cursor[dst]++ ; csr[pos] = src.
__global__ void k_csrfill(int E) {
    int i = blockIdx.x * blockDim.x + threadIdx.x;
    if (i >= E) return;
    int d = g_dst[i];
    int pos = atomicAdd(&g_cursor[d], 1);
    g_csr[pos] = g_src[i];
}

// ---------------------------------------------------------------------------
// Warp-cooperative 32-channel gather-sum over CSR edges of `node`.
// 4-way unrolled (independent accumulators) for MLP=4 per warp.
// ---------------------------------------------------------------------------
__device__ __forceinline__ float gather32(const float* __restrict__ h,
                                          int s0, int s1, int lane) {
    float a0 = 0.f, a1 = 0.f, a2 = 0.f, a3 = 0.f;
    for (int base = s0; base < s1; base += 32) {
        int e = base + lane;
        int sidx = (e < s1) ? __ldg(&g_csr[e]) : 0;
        int cnt = min(32, s1 - base);
        int k = 0;
        for (; k + 4 <= cnt; k += 4) {
            int i0 = __shfl_sync(0xffffffffu, sidx, k);
            int i1 = __shfl_sync(0xffffffffu, sidx, k + 1);
            int i2 = __shfl_sync(0xffffffffu, sidx, k + 2);
            int i3 = __shfl_sync(0xffffffffu, sidx, k + 3);
            a0 += __ldg(&h[i0 * 32 + lane]);
            a1 += __ldg(&h[i1 * 32 + lane]);
            a2 += __ldg(&h[i2 * 32 + lane]);
            a3 += __ldg(&h[i3 * 32 + lane]);
        }
        for (; k < cnt; k++) {
            int ik = __shfl_sync(0xffffffffu, sidx, k);
            a0 += __ldg(&h[ik * 32 + lane]);
        }
    }
    return (a0 + a1) + (a2 + a3);
}

// ---------------------------------------------------------------------------
// Layer 1: warp per node. Gather-sum of scalar x over CSR edges, then
// h1[node][lane] = lrelu(a*W1l[lane] + x[node]*W1r[lane] + b1[lane]).
// ---------------------------------------------------------------------------
__global__ void k_l1(const float* __restrict__ x, const float* __restrict__ W1l,
                     const float* __restrict__ b1, const float* __restrict__ W1r,
                     int N) {
    int lane = threadIdx.x & 31;
    int node = (blockIdx.x * blockDim.x + threadIdx.x) >> 5;
    if (node >= N) return;
    int s0 = g_rowptr[node], s1 = g_rowptr[node + 1];
    float a = 0.f;
    for (int j = s0 + lane; j < s1; j += 32) a += __ldg(&x[__ldg(&g_csr[j])]);
    #pragma unroll
    for (int off = 16; off > 0; off >>= 1) a += __shfl_xor_sync(0xffffffffu, a, off);
    float xv = __ldg(&x[node]);
    g_h1[node * 32 + lane] =
        lrelu(a * __ldg(&W1l[lane]) + xv * __ldg(&W1r[lane]) + __ldg(&b1[lane]));
}

// ---------------------------------------------------------------------------
// Layer 2: warp per node. Gather-sum h1[src] (coalesced 128B per edge),
// then fused shuffle GEMM: h2 = lrelu(agg@W2l + b2 + h1@W2r).
// ---------------------------------------------------------------------------
__global__ void k_sage2g(const float* __restrict__ Wl, const float* __restrict__ b,
                         const float* __restrict__ Wr, int N) {
    __shared__ float sWl[1024], sWr[1024], sb[32];
    for (int i = threadIdx.x; i < 1024; i += blockDim.x) { sWl[i] = Wl[i]; sWr[i] = Wr[i]; }
    if (threadIdx.x < 32) sb[threadIdx.x] = b[threadIdx.x];
    __syncthreads();
    int lane = threadIdx.x & 31;
    int node = (blockIdx.x * blockDim.x + threadIdx.x) >> 5;
    if (node >= N) return;
    int s0 = g_rowptr[node], s1 = g_rowptr[node + 1];
    float agg = gather32(g_h1, s0, s1, lane);
    float hv = g_h1[node * 32 + lane];
    float acc = sb[lane];
    #pragma unroll
    for (int k = 0; k < 32; k++) {
        acc += __shfl_sync(0xffffffffu, agg, k) * sWl[k * 32 + lane]
             + __shfl_sync(0xffffffffu, hv, k)  * sWr[k * 32 + lane];
    }
    g_h2[node * 32 + lane] = lrelu(acc);
}

// ---------------------------------------------------------------------------
// Layer 3 (mean) fused with up-projection: warp per node.
// h3 = lrelu((gather_sum(h2)/deg)@W3l + b3 + h2@W3r); h4 = lrelu(h3@Wu + bu)
// ---------------------------------------------------------------------------
__global__ void k_sage3g(const float* __restrict__ W3l, const float* __restrict__ b3,
                         const float* __restrict__ W3r, const float* __restrict__ Wu,
                         const float* __restrict__ bu, int N) {
    __shared__ float sWl[1024], sWr[1024], sWu[4096], sb[32], sbu[128];
    for (int i = threadIdx.x; i < 1024; i += blockDim.x) { sWl[i] = W3l[i]; sWr[i] = W3r[i]; }
    for (int i = threadIdx.x; i < 4096; i += blockDim.x) sWu[i] = Wu[i];
    if (threadIdx.x < 32)  sb[threadIdx.x]  = b3[threadIdx.x];
    if (threadIdx.x < 128) sbu[threadIdx.x] = bu[threadIdx.x];
    __syncthreads();
    int lane = threadIdx.x & 31;
    int node = (blockIdx.x * blockDim.x + threadIdx.x) >> 5;
    if (node >= N) return;
    int s0 = g_rowptr[node], s1 = g_rowptr[node + 1];
    float agg = gather32(g_h2, s0, s1, lane);
    float inv = 1.0f / fmaxf((float)(s1 - s0), 1.0f);
    agg *= inv;
    float hv = g_h2[node * 32 + lane];
    float acc = sb[lane];
    #pragma unroll
    for (int k = 0; k < 32; k++) {
        acc += __shfl_sync(0xffffffffu, agg, k) * sWl[k * 32 + lane]
             + __shfl_sync(0xffffffffu, hv, k)  * sWr[k * 32 + lane];
    }
    float h3 = lrelu(acc);
    float4 o = *(const float4*)(sbu + lane * 4);
    #pragma unroll
    for (int k = 0; k < 32; k++) {
        float hk = __shfl_sync(0xffffffffu, h3, k);
        float4 w = *(const float4*)(sWu + k * 128 + lane * 4);
        o.x += hk * w.x; o.y += hk * w.y; o.z += hk * w.z; o.w += hk * w.w;
    }
    o.x = lrelu(o.x); o.y = lrelu(o.y); o.z = lrelu(o.z); o.w = lrelu(o.w);
    *(float4*)(g_h4 + (size_t)node * 128 + lane * 4) = o;
}

// ---------------------------------------------------------------------------
// Per-graph start offsets from sorted batch array.
// ---------------------------------------------------------------------------
__global__ void k_starts(const void* __restrict__ batch, int N, int G) {
    int i = blockIdx.x * blockDim.x + threadIdx.x;
    if (i >= N) return;
    long long bi, bp;
    if (g_flags[1]) {
        const long long* p = (const long long*)batch;
        bi = p[i]; bp = (i == 0) ? -1LL : p[i - 1];
    } else {
        const int* p = (const int*)batch;
        bi = p[i]; bp = (i == 0) ? -1LL : p[i - 1];
    }
    if (bi != bp) for (long long g = bp + 1; g <= bi; g++) g_start[g] = i;
    if (i == N - 1) for (long long g = bi + 1; g <= G; g++) g_start[g] = N;
}

// ---------------------------------------------------------------------------
// Pooling partials: 4 blocks per graph, 128 threads (one per channel).
// g_part[(g*4+q)*256 + c] = partial sum, [+128] = partial max.
// ---------------------------------------------------------------------------
__global__ void k_pool(int G) {
    int g = blockIdx.x >> 2;
    int q = blockIdx.x & 3;
    int c = threadIdx.x;
    int s = g_start[g], e = g_start[g + 1];
    int len = e - s;
    int q0 = s + (len * q) / 4;
    int q1 = s + (len * (q + 1)) / 4;
    float sum = 0.f, mx = -INFINITY;
    for (int i = q0; i < q1; i++) {
        float v = g_h4[(size_t)i * 128 + c];
        sum += v;
        mx = fmaxf(mx, v);
    }
    g_part[(g * 4 + q) * 256 + c]       = sum;
    g_part[(g * 4 + q) * 256 + 128 + c] = mx;
}

// ---------------------------------------------------------------------------
// Head: combine partials -> z[384], then z -> lrelu(@Wf1+bf1) -> @Wf2+bf2.
// Block per graph, 128 threads.
// ---------------------------------------------------------------------------
__global__ void k_head(const float* __restrict__ Wf1, const float* __restrict__ bf1,
                       const float* __restrict__ Wf2, const float* __restrict__ bf2,
                       float* __restrict__ out, int G) {
    __shared__ float sz[384], sz2[128];
    int g = blockIdx.x;
    int c = threadIdx.x;
    float sum = 0.f, mx = -INFINITY;
    #pragma unroll
    for (int q = 0; q < 4; q++) {
        sum += g_part[(g * 4 + q) * 256 + c];
        mx = fmaxf(mx, g_part[(g * 4 + q) * 256 + 128 + c]);
    }
    float cnt = (float)(g_start[g + 1] - g_start[g]);
    sz[c]       = sum / fmaxf(cnt, 1.0f);
    sz[128 + c] = mx;
    sz[256 + c] = sum;
    __syncthreads();
    float acc = bf1[c];
    #pragma unroll 4
    for (int k = 0; k < 384; k++) acc += sz[k] * Wf1[k * 128 + c];
    sz2[c] = lrelu(acc);
    __syncthreads();
    if (c < 51) {
        float o = bf2[c];
        #pragma unroll 4
        for (int k = 0; k < 128; k++) o += sz2[k] * Wf2[k * 51 + c];
        out[g * 51 + c] = o;
    }
}

// ---------------------------------------------------------------------------
extern "C" void kernel_launch(void* const* d_in, const int* in_sizes, int n_in,
                              void* d_out, int out_size) {
    const float* x    = (const float*)d_in[0];
    const void*  eidx = d_in[1];
    const void*  batch= d_in[2];
    const float* W1l  = (const float*)d_in[3];
    const float* b1   = (const float*)d_in[4];
    const float* W1r  = (const float*)d_in[5];
    const float* W2l  = (const float*)d_in[6];
    const float* b2   = (const float*)d_in[7];
    const float* W2r  = (const float*)d_in[8];
    const float* W3l  = (const float*)d_in[9];
    const float* b3   = (const float*)d_in[10];
    const float* W3r  = (const float*)d_in[11];
    const float* Wu   = (const float*)d_in[12];
    const float* bu   = (const float*)d_in[13];
    const float* Wf1  = (const float*)d_in[14];
    const float* bf1  = (const float*)d_in[15];
    const float* Wf2  = (const float*)d_in[16];
    const float* bf2  = (const float*)d_in[17];
    float* out = (float*)d_out;

    int N = in_sizes[0];
    int E = in_sizes[1] / 2;
    int G = out_size / 51;

    int bbase = (N - 64) & ~1;
    int scan_blocks = (N + SCAN_BS - 1) / SCAN_BS;
    int node_warp_blocks = (N + 7) / 8;   // 256 threads = 8 warps, warp per node

    k_detect<<<1, 32>>>((const unsigned int*)eidx, (const unsigned int*)batch, bbase);
    k_zero_cnt<<<(N + 255) / 256, 256>>>(N);
    k_convert_hist<<<(E + 255) / 256, 256>>>(eidx, E);
    k_scanA<<<scan_blocks, SCAN_BS>>>(N);
    k_scanB<<<1, 32>>>(scan_blocks);
    k_scanC<<<(N + 255) / 256, 256>>>(N, E);
    k_csrfill<<<(E + 255) / 256, 256>>>(E);
    k_l1<<<node_warp_blocks, 256>>>(x, W1l, b1, W1r, N);
    k_sage2g<<<node_warp_blocks, 256>>>(W2l, b2, W2r, N);
    k_sage3g<<<node_warp_blocks, 256>>>(W3l, b3, W3r, Wu, bu, N);
    k_starts<<<(N + 255) / 256, 256>>>(batch, N, G);
    k_pool<<<G * 4, 128>>>(G);
    k_head<<<G, 128>>>(Wf1, bf1, Wf2, bf2, out, G);
}